// round 1
// baseline (speedup 1.0000x reference)
#include <cuda_runtime.h>
#include <math.h>

#define B_    64
#define NREF  256
#define NPTS  2048
#define DIM   128
#define EPSV  0.001f
#define SCALE (1.0f/EPSV)
#define LOG_WX (-5.5451748845f)   /* log(1/256 + 1e-8)  */
#define LOG_WY (-7.6245985065f)   /* log(1/2048 + 1e-8) */
#define ITERS 100
#define FULLM 0xffffffffu

// -------- device scratch (allocation-free per harness rules) --------
__device__ float g_C[(size_t)B_ * NREF * NPTS];   // 134 MB cost matrix
__device__ float g_u[B_ * NREF];
__device__ float g_v[B_ * NPTS];
__device__ float g_x2[B_ * NPTS];
__device__ float g_r2[NREF];

// -------- init u,v = 0 --------
__global__ void init_uv() {
    int t = blockIdx.x * blockDim.x + threadIdx.x;
    if (t < B_ * NREF) g_u[t] = 0.f;
    if (t < B_ * NPTS) g_v[t] = 0.f;
}

// -------- squared norms of X rows and reference rows --------
__global__ void aux_kernel(const float* __restrict__ X, const float* __restrict__ REF) {
    int gw   = (blockIdx.x * blockDim.x + threadIdx.x) >> 5;
    int lane = threadIdx.x & 31;
    if (gw < B_ * NPTS) {
        const float* r = X + (size_t)gw * DIM;
        float s = 0.f;
        #pragma unroll
        for (int k = lane; k < DIM; k += 32) { float t = r[k]; s = fmaf(t, t, s); }
        #pragma unroll
        for (int o = 16; o; o >>= 1) s += __shfl_xor_sync(FULLM, s, o);
        if (!lane) g_x2[gw] = s;
    } else if (gw < B_ * NPTS + NREF) {
        int i = gw - B_ * NPTS;
        const float* r = REF + i * DIM;
        float s = 0.f;
        #pragma unroll
        for (int k = lane; k < DIM; k += 32) { float t = r[k]; s = fmaf(t, t, s); }
        #pragma unroll
        for (int o = 16; o; o >>= 1) s += __shfl_xor_sync(FULLM, s, o);
        if (!lane) g_r2[i] = s;
    }
}

// -------- C[b,i,j] = sqrt(max(r2_i + x2_bj - 2*dot, 0)) : tiled fp32 GEMM --------
__global__ __launch_bounds__(256) void c_kernel(const float* __restrict__ X,
                                                const float* __restrict__ REF) {
    __shared__ float sA[32][65];   // ref tile, [k][ii]
    __shared__ float sB[32][65];   // X tile,   [k][jj]
    int b  = blockIdx.z;
    int i0 = blockIdx.y * 64, j0 = blockIdx.x * 64;
    int tid = threadIdx.x;
    int ti = tid >> 4, tj = tid & 15;
    const float* Xb = X + (size_t)b * NPTS * DIM;

    float acc[4][4];
    #pragma unroll
    for (int a = 0; a < 4; a++)
        #pragma unroll
        for (int c = 0; c < 4; c++) acc[a][c] = 0.f;

    for (int k0 = 0; k0 < DIM; k0 += 32) {
        #pragma unroll
        for (int r = 0; r < 8; r++) {
            int e  = r * 256 + tid;
            int ii = e >> 5, kk = e & 31;
            sA[kk][ii] = REF[(i0 + ii) * DIM + k0 + kk];
            sB[kk][ii] = Xb[(size_t)(j0 + ii) * DIM + k0 + kk];
        }
        __syncthreads();
        #pragma unroll
        for (int kk = 0; kk < 32; kk++) {
            float a0 = sA[kk][ti*4+0], a1 = sA[kk][ti*4+1], a2 = sA[kk][ti*4+2], a3 = sA[kk][ti*4+3];
            float b0 = sB[kk][tj*4+0], b1 = sB[kk][tj*4+1], b2 = sB[kk][tj*4+2], b3 = sB[kk][tj*4+3];
            acc[0][0]=fmaf(a0,b0,acc[0][0]); acc[0][1]=fmaf(a0,b1,acc[0][1]); acc[0][2]=fmaf(a0,b2,acc[0][2]); acc[0][3]=fmaf(a0,b3,acc[0][3]);
            acc[1][0]=fmaf(a1,b0,acc[1][0]); acc[1][1]=fmaf(a1,b1,acc[1][1]); acc[1][2]=fmaf(a1,b2,acc[1][2]); acc[1][3]=fmaf(a1,b3,acc[1][3]);
            acc[2][0]=fmaf(a2,b0,acc[2][0]); acc[2][1]=fmaf(a2,b1,acc[2][1]); acc[2][2]=fmaf(a2,b2,acc[2][2]); acc[2][3]=fmaf(a2,b3,acc[2][3]);
            acc[3][0]=fmaf(a3,b0,acc[3][0]); acc[3][1]=fmaf(a3,b1,acc[3][1]); acc[3][2]=fmaf(a3,b2,acc[3][2]); acc[3][3]=fmaf(a3,b3,acc[3][3]);
        }
        __syncthreads();
    }

    float x20 = g_x2[b*NPTS + j0 + tj*4 + 0];
    float x21 = g_x2[b*NPTS + j0 + tj*4 + 1];
    float x22 = g_x2[b*NPTS + j0 + tj*4 + 2];
    float x23 = g_x2[b*NPTS + j0 + tj*4 + 3];
    #pragma unroll
    for (int a = 0; a < 4; a++) {
        int i = i0 + ti*4 + a;
        float r2 = g_r2[i];
        float4 o;
        o.x = sqrtf(fmaxf(r2 + x20 - 2.f*acc[a][0], 0.f));
        o.y = sqrtf(fmaxf(r2 + x21 - 2.f*acc[a][1], 0.f));
        o.z = sqrtf(fmaxf(r2 + x22 - 2.f*acc[a][2], 0.f));
        o.w = sqrtf(fmaxf(r2 + x23 - 2.f*acc[a][3], 0.f));
        *(float4*)(&g_C[((size_t)b*NREF + i)*NPTS + j0 + tj*4]) = o;
    }
}

// -------- u update: u_i = eps*(log_wx - LSE_j((v_j - C_ij)/eps)) --------
// warp per row, z cached in registers, exp gated to active chunks only.
__global__ __launch_bounds__(256) void u_kernel() {
    __shared__ float vs[NPTS];
    int b = blockIdx.y;
    int tid = threadIdx.x, lane = tid & 31, w = tid >> 5;
    const float* vrow = g_v + b * NPTS;
    #pragma unroll
    for (int r = 0; r < NPTS/256; r++) vs[r*256 + tid] = vrow[r*256 + tid] * SCALE;
    __syncthreads();

    int i = blockIdx.x * 8 + w;
    const float* Crow = g_C + ((size_t)b*NREF + i) * NPTS;

    float z[64];
    float m = __int_as_float(0xff800000);
    #pragma unroll
    for (int k = 0; k < 64; k++) {
        int j = k*32 + lane;
        z[k] = fmaf(-SCALE, Crow[j], vs[j]);
        m = fmaxf(m, z[k]);
    }
    #pragma unroll
    for (int o = 16; o; o >>= 1) m = fmaxf(m, __shfl_xor_sync(FULLM, m, o));

    float s = 0.f;
    #pragma unroll
    for (int k = 0; k < 64; k++) {
        float d = z[k] - m;
        if (__any_sync(FULLM, d > -25.f)) {   // rare: exp only near the max
            if (d > -25.f) s += __expf(d);
        }
    }
    #pragma unroll
    for (int o = 16; o; o >>= 1) s += __shfl_xor_sync(FULLM, s, o);

    if (!lane) g_u[b*NREF + i] = EPSV * (LOG_WX - (m + __logf(s)));
}

// -------- v update: v_j = eps*(log_wy - LSE_i((u_i - C_ij)/eps)) --------
// thread per column, online LSE; exp only on new-max or near-max.
__global__ __launch_bounds__(256) void v_kernel() {
    __shared__ float us[NREF];
    int b = blockIdx.y;
    int tid = threadIdx.x;
    us[tid] = g_u[b*NREF + tid] * SCALE;
    __syncthreads();

    int j = blockIdx.x * 256 + tid;
    const float* Cp = g_C + (size_t)b * NREF * NPTS + j;

    float m = __int_as_float(0xff800000), s = 0.f;
    #pragma unroll 8
    for (int i = 0; i < NREF; i++) {
        float z = fmaf(-SCALE, Cp[(size_t)i * NPTS], us[i]);
        float d = z - m;
        if (d > 0.f)        { s = fmaf(s, __expf(-d), 1.f); m = z; }
        else if (d > -25.f) { s += __expf(d); }
    }
    g_v[b*NPTS + j] = EPSV * (LOG_WY - (m + __logf(s)));
}

// -------- barycenters: out[b,i,:] = (sum_j P_ij X_j)/(sum_j P_ij + 1e-8) - ref_i --------
// P is near one-hot: sparse accumulation via ballot over active lanes.
__global__ __launch_bounds__(256) void bary_kernel(const float* __restrict__ X,
                                                   const float* __restrict__ REF,
                                                   float* __restrict__ out) {
    __shared__ float vs[NPTS];
    int b = blockIdx.y, tid = threadIdx.x, lane = tid & 31, w = tid >> 5;
    const float* vrow = g_v + b * NPTS;
    #pragma unroll
    for (int r = 0; r < NPTS/256; r++) vs[r*256 + tid] = vrow[r*256 + tid] * SCALE;
    __syncthreads();

    int i = blockIdx.x * 8 + w;
    float ui = g_u[b*NREF + i] * SCALE;
    const float* Crow = g_C + ((size_t)b*NREF + i) * NPTS;
    const float* Xb   = X + (size_t)b * NPTS * DIM;

    float acc0 = 0.f, acc1 = 0.f, acc2 = 0.f, acc3 = 0.f, den = 0.f;
    for (int jb = 0; jb < NPTS; jb += 32) {
        int j = jb + lane;
        float z = fmaf(-SCALE, Crow[j], ui + vs[j]);
        float wgt = 0.f;
        if (z > -60.f) wgt = __expf(z);
        unsigned act = __ballot_sync(FULLM, z > -60.f);
        while (act) {
            int p = __ffs(act) - 1; act &= act - 1;
            float wj = __shfl_sync(FULLM, wgt, p);
            const float* xr = Xb + (size_t)(jb + p) * DIM;
            acc0 = fmaf(wj, xr[lane     ], acc0);
            acc1 = fmaf(wj, xr[lane + 32], acc1);
            acc2 = fmaf(wj, xr[lane + 64], acc2);
            acc3 = fmaf(wj, xr[lane + 96], acc3);
            den += wj;
        }
    }
    float inv = 1.f / (den + 1e-8f);
    float* orow = out + ((size_t)b*NREF + i) * DIM;
    orow[lane     ] = acc0 * inv - REF[i*DIM + lane     ];
    orow[lane + 32] = acc1 * inv - REF[i*DIM + lane + 32];
    orow[lane + 64] = acc2 * inv - REF[i*DIM + lane + 64];
    orow[lane + 96] = acc3 * inv - REF[i*DIM + lane + 96];
}

extern "C" void kernel_launch(void* const* d_in, const int* in_sizes, int n_in,
                              void* d_out, int out_size) {
    const float* a = (const float*)d_in[0];
    const float* c = (const float*)d_in[1];
    const float *X, *REF;
    if (in_sizes[0] == NREF * DIM) { REF = a; X = c; }
    else                           { X = a;  REF = c; }
    float* out = (float*)d_out;

    init_uv<<<(B_*NPTS + 255) / 256, 256>>>();

    int warps = B_*NPTS + NREF;
    aux_kernel<<<(warps*32 + 255) / 256, 256>>>(X, REF);

    dim3 cg(NPTS/64, NREF/64, B_);
    c_kernel<<<cg, 256>>>(X, REF);

    for (int it = 0; it < ITERS; it++) {
        u_kernel<<<dim3(NREF/8, B_), 256>>>();
        v_kernel<<<dim3(NPTS/256, B_), 256>>>();
    }

    bary_kernel<<<dim3(NREF/8, B_), 256>>>(X, REF, out);
}

// round 2
// speedup vs baseline: 1.4656x; 1.4656x over previous
#include <cuda_runtime.h>
#include <math.h>

#define B_    64
#define NREF  256
#define NPTS  2048
#define DIM   128
#define EPSV  0.001f
#define SCALE 1000.0f
#define LOG_WX (-5.5451748845f)   /* log(1/256 + 1e-8)  */
#define LOG_WY (-7.6245985065f)   /* log(1/2048 + 1e-8) */
#define ITERS 100
#define FULLM 0xffffffffu
#define NEG_INF __int_as_float(0xff800000)
#define TOLS  0.02f               /* convergence tol in scaled (exponent) units */

// -------- device scratch (allocation-free per harness rules) --------
__device__ float g_C[(size_t)B_ * NREF * NPTS];   // 134 MB cost matrix
__device__ float g_us[B_ * NREF];                 // scaled potentials u/eps
__device__ float g_vs[B_ * NPTS];                 // scaled potentials v/eps
__device__ float g_x2[B_ * NPTS];
__device__ float g_r2[NREF];

// -------- squared norms of X rows and reference rows --------
__global__ void aux_kernel(const float* __restrict__ X, const float* __restrict__ REF) {
    int gw   = (blockIdx.x * blockDim.x + threadIdx.x) >> 5;
    int lane = threadIdx.x & 31;
    if (gw < B_ * NPTS) {
        const float* r = X + (size_t)gw * DIM;
        float s = 0.f;
        #pragma unroll
        for (int k = lane; k < DIM; k += 32) { float t = r[k]; s = fmaf(t, t, s); }
        #pragma unroll
        for (int o = 16; o; o >>= 1) s += __shfl_xor_sync(FULLM, s, o);
        if (!lane) g_x2[gw] = s;
    } else if (gw < B_ * NPTS + NREF) {
        int i = gw - B_ * NPTS;
        const float* r = REF + i * DIM;
        float s = 0.f;
        #pragma unroll
        for (int k = lane; k < DIM; k += 32) { float t = r[k]; s = fmaf(t, t, s); }
        #pragma unroll
        for (int o = 16; o; o >>= 1) s += __shfl_xor_sync(FULLM, s, o);
        if (!lane) g_r2[i] = s;
    }
}

// -------- C[b,i,j] = sqrt(max(r2_i + x2_bj - 2*dot, 0)) : tiled fp32 GEMM --------
__global__ __launch_bounds__(256) void c_kernel(const float* __restrict__ X,
                                                const float* __restrict__ REF) {
    __shared__ float sA[32][65];
    __shared__ float sB[32][65];
    int b  = blockIdx.z;
    int i0 = blockIdx.y * 64, j0 = blockIdx.x * 64;
    int tid = threadIdx.x;
    int ti = tid >> 4, tj = tid & 15;
    const float* Xb = X + (size_t)b * NPTS * DIM;

    float acc[4][4];
    #pragma unroll
    for (int a = 0; a < 4; a++)
        #pragma unroll
        for (int c = 0; c < 4; c++) acc[a][c] = 0.f;

    for (int k0 = 0; k0 < DIM; k0 += 32) {
        #pragma unroll
        for (int r = 0; r < 8; r++) {
            int e  = r * 256 + tid;
            int ii = e >> 5, kk = e & 31;
            sA[kk][ii] = REF[(i0 + ii) * DIM + k0 + kk];
            sB[kk][ii] = Xb[(size_t)(j0 + ii) * DIM + k0 + kk];
        }
        __syncthreads();
        #pragma unroll
        for (int kk = 0; kk < 32; kk++) {
            float a0 = sA[kk][ti*4+0], a1 = sA[kk][ti*4+1], a2 = sA[kk][ti*4+2], a3 = sA[kk][ti*4+3];
            float b0 = sB[kk][tj*4+0], b1 = sB[kk][tj*4+1], b2 = sB[kk][tj*4+2], b3 = sB[kk][tj*4+3];
            acc[0][0]=fmaf(a0,b0,acc[0][0]); acc[0][1]=fmaf(a0,b1,acc[0][1]); acc[0][2]=fmaf(a0,b2,acc[0][2]); acc[0][3]=fmaf(a0,b3,acc[0][3]);
            acc[1][0]=fmaf(a1,b0,acc[1][0]); acc[1][1]=fmaf(a1,b1,acc[1][1]); acc[1][2]=fmaf(a1,b2,acc[1][2]); acc[1][3]=fmaf(a1,b3,acc[1][3]);
            acc[2][0]=fmaf(a2,b0,acc[2][0]); acc[2][1]=fmaf(a2,b1,acc[2][1]); acc[2][2]=fmaf(a2,b2,acc[2][2]); acc[2][3]=fmaf(a2,b3,acc[2][3]);
            acc[3][0]=fmaf(a3,b0,acc[3][0]); acc[3][1]=fmaf(a3,b1,acc[3][1]); acc[3][2]=fmaf(a3,b2,acc[3][2]); acc[3][3]=fmaf(a3,b3,acc[3][3]);
        }
        __syncthreads();
    }

    float x20 = g_x2[b*NPTS + j0 + tj*4 + 0];
    float x21 = g_x2[b*NPTS + j0 + tj*4 + 1];
    float x22 = g_x2[b*NPTS + j0 + tj*4 + 2];
    float x23 = g_x2[b*NPTS + j0 + tj*4 + 3];
    #pragma unroll
    for (int a = 0; a < 4; a++) {
        int i = i0 + ti*4 + a;
        float r2 = g_r2[i];
        float4 o;
        o.x = sqrtf(fmaxf(r2 + x20 - 2.f*acc[a][0], 0.f));
        o.y = sqrtf(fmaxf(r2 + x21 - 2.f*acc[a][1], 0.f));
        o.z = sqrtf(fmaxf(r2 + x22 - 2.f*acc[a][2], 0.f));
        o.w = sqrtf(fmaxf(r2 + x23 - 2.f*acc[a][3], 0.f));
        *(float4*)(&g_C[((size_t)b*NREF + i)*NPTS + j0 + tj*4]) = o;
    }
}

// -------- persistent Sinkhorn: one block per batch, all iterations internal --------
__global__ __launch_bounds__(1024, 1) void sinkhorn_persist() {
    __shared__ __align__(16) float us[NREF];
    __shared__ __align__(16) float vs[NPTS];
    __shared__ float red[32];
    __shared__ int   s_done;

    int b = blockIdx.x;
    int tid = threadIdx.x, lane = tid & 31, w = tid >> 5;
    const float* Cb = g_C + (size_t)b * NREF * NPTS;

    if (tid < NREF) us[tid] = 0.f;
    vs[tid] = 0.f; vs[tid + 1024] = 0.f;
    if (tid == 0) s_done = 0;
    __syncthreads();

    for (int iter = 0; iter < ITERS; iter++) {
        float dmax = 0.f;

        // ---- u phase: warp w -> rows w*8 .. w*8+7, online LSE over 2048 cols
        #pragma unroll 1
        for (int r = 0; r < 8; r++) {
            int i = w * 8 + r;
            const float4* Crow = (const float4*)(Cb + (size_t)i * NPTS);
            float m = NEG_INF, s = 0.f;
            #pragma unroll 4
            for (int k = lane; k < NPTS/4; k += 32) {
                float4 c  = Crow[k];
                float4 vv = *(const float4*)&vs[k*4];
                float z0 = fmaf(-SCALE, c.x, vv.x);
                float z1 = fmaf(-SCALE, c.y, vv.y);
                float z2 = fmaf(-SCALE, c.z, vv.z);
                float z3 = fmaf(-SCALE, c.w, vv.w);
                float lm = fmaxf(fmaxf(z0, z1), fmaxf(z2, z3));
                if (lm > m - 25.f) {                 // rare after warm-up
                    float nm = fmaxf(m, lm);
                    s *= __expf(m - nm);
                    if (z0 > nm - 25.f) s += __expf(z0 - nm);
                    if (z1 > nm - 25.f) s += __expf(z1 - nm);
                    if (z2 > nm - 25.f) s += __expf(z2 - nm);
                    if (z3 > nm - 25.f) s += __expf(z3 - nm);
                    m = nm;
                }
            }
            #pragma unroll
            for (int o = 16; o; o >>= 1) {
                float mo = __shfl_xor_sync(FULLM, m, o);
                float so = __shfl_xor_sync(FULLM, s, o);
                float nm = fmaxf(m, mo);
                s = s * __expf(m - nm) + so * __expf(mo - nm);
                m = nm;
            }
            float nu = LOG_WX - (m + __logf(s));
            if (lane == 0) {
                dmax = fmaxf(dmax, fabsf(nu - us[i]));
                us[i] = nu;
            }
        }
        __syncthreads();

        // ---- v phase: thread -> cols 2*tid, 2*tid+1, online LSE over 256 rows
        {
            const float2* Cc = (const float2*)Cb;
            float m0 = NEG_INF, s0 = 0.f, m1 = NEG_INF, s1 = 0.f;
            for (int i0 = 0; i0 < NREF; i0 += 8) {
                float2 c[8];
                #pragma unroll
                for (int q = 0; q < 8; q++)
                    c[q] = Cc[(size_t)(i0 + q) * (NPTS/2) + tid];
                #pragma unroll
                for (int q = 0; q < 8; q++) {
                    float uu = us[i0 + q];
                    float z0 = fmaf(-SCALE, c[q].x, uu);
                    float z1 = fmaf(-SCALE, c[q].y, uu);
                    if (z0 > m0 - 25.f) {
                        float nm = fmaxf(m0, z0);
                        s0 = s0 * __expf(m0 - nm) + __expf(z0 - nm);
                        m0 = nm;
                    }
                    if (z1 > m1 - 25.f) {
                        float nm = fmaxf(m1, z1);
                        s1 = s1 * __expf(m1 - nm) + __expf(z1 - nm);
                        m1 = nm;
                    }
                }
            }
            float nv0 = LOG_WY - (m0 + __logf(s0));
            float nv1 = LOG_WY - (m1 + __logf(s1));
            dmax = fmaxf(dmax, fmaxf(fabsf(nv0 - vs[2*tid]), fabsf(nv1 - vs[2*tid+1])));
            vs[2*tid]     = nv0;
            vs[2*tid + 1] = nv1;
        }

        // ---- convergence reduction + early exit
        #pragma unroll
        for (int o = 16; o; o >>= 1) dmax = fmaxf(dmax, __shfl_xor_sync(FULLM, dmax, o));
        if (lane == 0) red[w] = dmax;
        __syncthreads();
        if (tid == 0) {
            float dm = 0.f;
            #pragma unroll
            for (int q = 0; q < 32; q++) dm = fmaxf(dm, red[q]);
            s_done = (dm < TOLS) ? 1 : 0;
        }
        __syncthreads();
        if (s_done) break;
    }

    if (tid < NREF) g_us[b*NREF + tid] = us[tid];
    g_vs[b*NPTS + tid]        = vs[tid];
    g_vs[b*NPTS + tid + 1024] = vs[tid + 1024];
}

// -------- barycenters: near one-hot P -> sparse ballot-gather of X rows --------
__global__ __launch_bounds__(256) void bary_kernel(const float* __restrict__ X,
                                                   const float* __restrict__ REF,
                                                   float* __restrict__ out) {
    __shared__ float vsb[NPTS];
    int b = blockIdx.y, tid = threadIdx.x, lane = tid & 31, w = tid >> 5;
    const float* vrow = g_vs + b * NPTS;
    #pragma unroll
    for (int r = 0; r < NPTS/256; r++) vsb[r*256 + tid] = vrow[r*256 + tid];
    __syncthreads();

    int i = blockIdx.x * 8 + w;
    float ui = g_us[b*NREF + i];
    const float* Crow = g_C + ((size_t)b*NREF + i) * NPTS;
    const float* Xb   = X + (size_t)b * NPTS * DIM;

    float acc0 = 0.f, acc1 = 0.f, acc2 = 0.f, acc3 = 0.f, den = 0.f;
    for (int jb = 0; jb < NPTS; jb += 32) {
        int j = jb + lane;
        float z = fmaf(-SCALE, Crow[j], ui + vsb[j]);
        float wgt = 0.f;
        if (z > -60.f) wgt = __expf(z);
        unsigned act = __ballot_sync(FULLM, z > -60.f);
        while (act) {
            int p = __ffs(act) - 1; act &= act - 1;
            float wj = __shfl_sync(FULLM, wgt, p);
            const float* xr = Xb + (size_t)(jb + p) * DIM;
            acc0 = fmaf(wj, xr[lane     ], acc0);
            acc1 = fmaf(wj, xr[lane + 32], acc1);
            acc2 = fmaf(wj, xr[lane + 64], acc2);
            acc3 = fmaf(wj, xr[lane + 96], acc3);
            den += wj;
        }
    }
    float inv = 1.f / (den + 1e-8f);
    float* orow = out + ((size_t)b*NREF + i) * DIM;
    orow[lane     ] = acc0 * inv - REF[i*DIM + lane     ];
    orow[lane + 32] = acc1 * inv - REF[i*DIM + lane + 32];
    orow[lane + 64] = acc2 * inv - REF[i*DIM + lane + 64];
    orow[lane + 96] = acc3 * inv - REF[i*DIM + lane + 96];
}

extern "C" void kernel_launch(void* const* d_in, const int* in_sizes, int n_in,
                              void* d_out, int out_size) {
    const float* a = (const float*)d_in[0];
    const float* c = (const float*)d_in[1];
    const float *X, *REF;
    if (in_sizes[0] == NREF * DIM) { REF = a; X = c; }
    else                           { X = a;  REF = c; }
    float* out = (float*)d_out;

    int warps = B_*NPTS + NREF;
    aux_kernel<<<(warps*32 + 255) / 256, 256>>>(X, REF);

    dim3 cg(NPTS/64, NREF/64, B_);
    c_kernel<<<cg, 256>>>(X, REF);

    sinkhorn_persist<<<B_, 1024>>>();

    bary_kernel<<<dim3(NREF/8, B_), 256>>>(X, REF, out);
}

// round 4
// speedup vs baseline: 2.2986x; 1.5683x over previous
#include <cuda_runtime.h>
#include <cstdint>
#include <math.h>

#define B_    64
#define NREF  256
#define NPTS  2048
#define DIM   128
#define EPSV  0.001f
#define SCALE 1000.0f
#define LOG_WX (-5.5451748845f)   /* log(1/256 + 1e-8)  */
#define LOG_WY (-7.6245985065f)   /* log(1/2048 + 1e-8) */
#define ITERS 100
#define FULLM 0xffffffffu
#define NEG_INF __int_as_float(0xff800000)
#define TOLS  0.02f

// -------- device scratch (allocation-free per harness rules) --------
__device__ float g_C[(size_t)B_ * NREF * NPTS];   // 134 MB cost matrix
__device__ float g_us[B_ * NREF];                 // scaled potentials u/eps
__device__ float g_vs[B_ * NPTS];                 // scaled potentials v/eps
__device__ float g_x2[B_ * NPTS];
__device__ float g_r2[NREF];

__device__ __forceinline__ unsigned int smem_u32(const void* p) {
    unsigned int a;
    asm("{ .reg .u64 t; cvta.to.shared.u64 t, %1; cvt.u32.u64 %0, t; }" : "=r"(a) : "l"(p));
    return a;
}
__device__ __forceinline__ void st_peer_f32(unsigned int local_addr, int peer, float v) {
    unsigned int rem;
    asm volatile("mapa.shared::cluster.u32 %0, %1, %2;" : "=r"(rem) : "r"(local_addr), "r"(peer));
    asm volatile("st.shared::cluster.f32 [%0], %1;" :: "r"(rem), "f"(v) : "memory");
}
__device__ __forceinline__ void cluster_sync_() {
    asm volatile("barrier.cluster.arrive.aligned;" ::: "memory");
    asm volatile("barrier.cluster.wait.aligned;" ::: "memory");
}

// -------- squared norms of X rows and reference rows --------
__global__ void aux_kernel(const float* __restrict__ X, const float* __restrict__ REF) {
    int gw   = (blockIdx.x * blockDim.x + threadIdx.x) >> 5;
    int lane = threadIdx.x & 31;
    if (gw < B_ * NPTS) {
        const float* r = X + (size_t)gw * DIM;
        float s = 0.f;
        #pragma unroll
        for (int k = lane; k < DIM; k += 32) { float t = r[k]; s = fmaf(t, t, s); }
        #pragma unroll
        for (int o = 16; o; o >>= 1) s += __shfl_xor_sync(FULLM, s, o);
        if (!lane) g_x2[gw] = s;
    } else if (gw < B_ * NPTS + NREF) {
        int i = gw - B_ * NPTS;
        const float* r = REF + i * DIM;
        float s = 0.f;
        #pragma unroll
        for (int k = lane; k < DIM; k += 32) { float t = r[k]; s = fmaf(t, t, s); }
        #pragma unroll
        for (int o = 16; o; o >>= 1) s += __shfl_xor_sync(FULLM, s, o);
        if (!lane) g_r2[i] = s;
    }
}

// -------- C[b,i,j] = sqrt(max(r2_i + x2_bj - 2*dot, 0)) : tiled fp32 GEMM --------
__global__ __launch_bounds__(256) void c_kernel(const float* __restrict__ X,
                                                const float* __restrict__ REF) {
    __shared__ float sA[32][65];
    __shared__ float sB[32][65];
    int b  = blockIdx.z;
    int i0 = blockIdx.y * 64, j0 = blockIdx.x * 64;
    int tid = threadIdx.x;
    int ti = tid >> 4, tj = tid & 15;
    const float* Xb = X + (size_t)b * NPTS * DIM;

    float acc[4][4];
    #pragma unroll
    for (int a = 0; a < 4; a++)
        #pragma unroll
        for (int c = 0; c < 4; c++) acc[a][c] = 0.f;

    for (int k0 = 0; k0 < DIM; k0 += 32) {
        #pragma unroll
        for (int r = 0; r < 8; r++) {
            int e  = r * 256 + tid;
            int ii = e >> 5, kk = e & 31;
            sA[kk][ii] = REF[(i0 + ii) * DIM + k0 + kk];
            sB[kk][ii] = Xb[(size_t)(j0 + ii) * DIM + k0 + kk];
        }
        __syncthreads();
        #pragma unroll
        for (int kk = 0; kk < 32; kk++) {
            float a0 = sA[kk][ti*4+0], a1 = sA[kk][ti*4+1], a2 = sA[kk][ti*4+2], a3 = sA[kk][ti*4+3];
            float b0 = sB[kk][tj*4+0], b1 = sB[kk][tj*4+1], b2 = sB[kk][tj*4+2], b3 = sB[kk][tj*4+3];
            acc[0][0]=fmaf(a0,b0,acc[0][0]); acc[0][1]=fmaf(a0,b1,acc[0][1]); acc[0][2]=fmaf(a0,b2,acc[0][2]); acc[0][3]=fmaf(a0,b3,acc[0][3]);
            acc[1][0]=fmaf(a1,b0,acc[1][0]); acc[1][1]=fmaf(a1,b1,acc[1][1]); acc[1][2]=fmaf(a1,b2,acc[1][2]); acc[1][3]=fmaf(a1,b3,acc[1][3]);
            acc[2][0]=fmaf(a2,b0,acc[2][0]); acc[2][1]=fmaf(a2,b1,acc[2][1]); acc[2][2]=fmaf(a2,b2,acc[2][2]); acc[2][3]=fmaf(a2,b3,acc[2][3]);
            acc[3][0]=fmaf(a3,b0,acc[3][0]); acc[3][1]=fmaf(a3,b1,acc[3][1]); acc[3][2]=fmaf(a3,b2,acc[3][2]); acc[3][3]=fmaf(a3,b3,acc[3][3]);
        }
        __syncthreads();
    }

    float x20 = g_x2[b*NPTS + j0 + tj*4 + 0];
    float x21 = g_x2[b*NPTS + j0 + tj*4 + 1];
    float x22 = g_x2[b*NPTS + j0 + tj*4 + 2];
    float x23 = g_x2[b*NPTS + j0 + tj*4 + 3];
    #pragma unroll
    for (int a = 0; a < 4; a++) {
        int i = i0 + ti*4 + a;
        float r2 = g_r2[i];
        float4 o;
        o.x = sqrtf(fmaxf(r2 + x20 - 2.f*acc[a][0], 0.f));
        o.y = sqrtf(fmaxf(r2 + x21 - 2.f*acc[a][1], 0.f));
        o.z = sqrtf(fmaxf(r2 + x22 - 2.f*acc[a][2], 0.f));
        o.w = sqrtf(fmaxf(r2 + x23 - 2.f*acc[a][3], 0.f));
        *(float4*)(&g_C[((size_t)b*NREF + i)*NPTS + j0 + tj*4]) = o;
    }
}

// -------- cluster-parallel Sinkhorn: 2 CTAs per batch, all iterations internal --------
// CTA rank r: rows [128r,128r+128) in u-phase, cols [1024r,1024r+1024) in v-phase.
// Fresh potentials pushed into peer SMEM via st.shared::cluster; barrier.cluster publishes.
__global__ __launch_bounds__(1024, 1) __cluster_dims__(2, 1, 1)
void sinkhorn_cluster() {
    __shared__ __align__(16) float us[NREF];
    __shared__ __align__(16) float vs[NPTS];
    __shared__ float red[32];
    __shared__ float dm2[2];

    int b    = blockIdx.x >> 1;
    int rank = blockIdx.x & 1;
    int peer = rank ^ 1;
    int tid = threadIdx.x, lane = tid & 31, w = tid >> 5;
    const float* Cb = g_C + (size_t)b * NREF * NPTS;

    unsigned int us_a = smem_u32(us);
    unsigned int vs_a = smem_u32(vs);
    unsigned int dm_a = smem_u32(dm2);

    if (tid < NREF) us[tid] = 0.f;
    vs[tid] = 0.f; vs[tid + 1024] = 0.f;
    __syncthreads();
    cluster_sync_();

    for (int iter = 0; iter < ITERS; iter++) {
        float dmax = 0.f;

        // ---- u phase: this CTA owns 128 rows; warp w -> 4 rows
        #pragma unroll 1
        for (int r = 0; r < 4; r++) {
            int i = rank * 128 + w * 4 + r;
            const float4* Crow = (const float4*)(Cb + (size_t)i * NPTS);
            float m = NEG_INF, s = 0.f;
            #pragma unroll 4
            for (int k = lane; k < NPTS/4; k += 32) {
                float4 c  = Crow[k];
                float4 vv = *(const float4*)&vs[k*4];
                float z0 = fmaf(-SCALE, c.x, vv.x);
                float z1 = fmaf(-SCALE, c.y, vv.y);
                float z2 = fmaf(-SCALE, c.z, vv.z);
                float z3 = fmaf(-SCALE, c.w, vv.w);
                float lm = fmaxf(fmaxf(z0, z1), fmaxf(z2, z3));
                if (lm > m - 25.f) {
                    float nm = fmaxf(m, lm);
                    s *= __expf(m - nm);
                    if (z0 > nm - 25.f) s += __expf(z0 - nm);
                    if (z1 > nm - 25.f) s += __expf(z1 - nm);
                    if (z2 > nm - 25.f) s += __expf(z2 - nm);
                    if (z3 > nm - 25.f) s += __expf(z3 - nm);
                    m = nm;
                }
            }
            #pragma unroll
            for (int o = 16; o; o >>= 1) {
                float mo = __shfl_xor_sync(FULLM, m, o);
                float so = __shfl_xor_sync(FULLM, s, o);
                float nm = fmaxf(m, mo);
                s = s * __expf(m - nm) + so * __expf(mo - nm);
                m = nm;
            }
            float nu = LOG_WX - (m + __logf(s));
            if (lane == 0) {
                dmax = fmaxf(dmax, fabsf(nu - us[i]));
                us[i] = nu;
                st_peer_f32(us_a + 4u*i, peer, nu);
            }
        }
        __syncthreads();          // local us half complete
        cluster_sync_();          // publish; both halves now visible

        // ---- v phase: this CTA owns 1024 cols; 1 col per thread
        {
            int j = rank * 1024 + tid;
            const float* Cp = Cb + j;
            float m0 = NEG_INF, s0 = 0.f;
            for (int i0 = 0; i0 < NREF; i0 += 8) {
                float c[8];
                #pragma unroll
                for (int q = 0; q < 8; q++)
                    c[q] = Cp[(size_t)(i0 + q) * NPTS];
                #pragma unroll
                for (int q = 0; q < 8; q++) {
                    float z0 = fmaf(-SCALE, c[q], us[i0 + q]);
                    if (z0 > m0 - 25.f) {
                        float nm = fmaxf(m0, z0);
                        s0 = s0 * __expf(m0 - nm) + __expf(z0 - nm);
                        m0 = nm;
                    }
                }
            }
            float nv = LOG_WY - (m0 + __logf(s0));
            dmax = fmaxf(dmax, fabsf(nv - vs[j]));
            vs[j] = nv;
            st_peer_f32(vs_a + 4u*j, peer, nv);
        }

        // ---- dmax reduction, exchange, uniform break
        #pragma unroll
        for (int o = 16; o; o >>= 1) dmax = fmaxf(dmax, __shfl_xor_sync(FULLM, dmax, o));
        if (lane == 0) red[w] = dmax;
        __syncthreads();
        if (tid == 0) {
            float dm = 0.f;
            #pragma unroll
            for (int q = 0; q < 32; q++) dm = fmaxf(dm, red[q]);
            dm2[rank] = dm;
            st_peer_f32(dm_a + 4u*rank, peer, dm);
        }
        __syncthreads();          // vs half + dm written locally
        cluster_sync_();          // publish vs + dm
        if (fmaxf(dm2[0], dm2[1]) < TOLS) break;
    }

    if (rank == 0) {
        if (tid < NREF) g_us[b*NREF + tid] = us[tid];
        g_vs[b*NPTS + tid]        = vs[tid];
        g_vs[b*NPTS + tid + 1024] = vs[tid + 1024];
    }
    cluster_sync_();   // peer SMEM stays alive until exports done
}

// -------- barycenters: near one-hot P -> float4 scan + sparse ballot gather --------
__global__ __launch_bounds__(256) void bary_kernel(const float* __restrict__ X,
                                                   const float* __restrict__ REF,
                                                   float* __restrict__ out) {
    __shared__ float vsb[NPTS];
    int b = blockIdx.y, tid = threadIdx.x, lane = tid & 31, w = tid >> 5;
    const float* vrow = g_vs + b * NPTS;
    #pragma unroll
    for (int r = 0; r < NPTS/256; r++) vsb[r*256 + tid] = vrow[r*256 + tid];
    __syncthreads();

    int i = blockIdx.x * 8 + w;
    float ui = g_us[b*NREF + i];
    const float4* Crow4 = (const float4*)(g_C + ((size_t)b*NREF + i) * NPTS);
    const float* Xb   = X + (size_t)b * NPTS * DIM;

    float acc0 = 0.f, acc1 = 0.f, acc2 = 0.f, acc3 = 0.f, den = 0.f;
    for (int jb = 0; jb < NPTS; jb += 128) {          // 128 cols per warp pass
        int q4 = (jb >> 2) + lane;                    // float4 index: cols jb+4*lane..+3
        float4 c  = Crow4[q4];
        float4 vv = *(const float4*)&vsb[jb + 4*lane];
        float z0 = fmaf(-SCALE, c.x, ui + vv.x);
        float z1 = fmaf(-SCALE, c.y, ui + vv.y);
        float z2 = fmaf(-SCALE, c.z, ui + vv.z);
        float z3 = fmaf(-SCALE, c.w, ui + vv.w);
        float zm = fmaxf(fmaxf(z0, z1), fmaxf(z2, z3));
        unsigned act = __ballot_sync(FULLM, zm > -60.f);
        if (!act) continue;
        float w0 = 0.f, w1 = 0.f, w2 = 0.f, w3 = 0.f;
        unsigned fl = 0;
        if (zm > -60.f) {
            if (z0 > -60.f) { w0 = __expf(z0); fl |= 1; }
            if (z1 > -60.f) { w1 = __expf(z1); fl |= 2; }
            if (z2 > -60.f) { w2 = __expf(z2); fl |= 4; }
            if (z3 > -60.f) { w3 = __expf(z3); fl |= 8; }
        }
        while (act) {
            int p = __ffs(act) - 1; act &= act - 1;
            unsigned mf = __shfl_sync(FULLM, fl, p);
            float a0 = __shfl_sync(FULLM, w0, p);
            float a1 = __shfl_sync(FULLM, w1, p);
            float a2 = __shfl_sync(FULLM, w2, p);
            float a3 = __shfl_sync(FULLM, w3, p);
            int jbase = jb + 4*p;
            #pragma unroll
            for (int q = 0; q < 4; q++) {
                float wj = (q==0) ? a0 : (q==1) ? a1 : (q==2) ? a2 : a3;
                if (mf & (1u << q)) {
                    const float* xr = Xb + (size_t)(jbase + q) * DIM;
                    acc0 = fmaf(wj, xr[lane     ], acc0);
                    acc1 = fmaf(wj, xr[lane + 32], acc1);
                    acc2 = fmaf(wj, xr[lane + 64], acc2);
                    acc3 = fmaf(wj, xr[lane + 96], acc3);
                    den += wj;
                }
            }
        }
    }
    float inv = 1.f / (den + 1e-8f);
    float* orow = out + ((size_t)b*NREF + i) * DIM;
    orow[lane     ] = acc0 * inv - REF[i*DIM + lane     ];
    orow[lane + 32] = acc1 * inv - REF[i*DIM + lane + 32];
    orow[lane + 64] = acc2 * inv - REF[i*DIM + lane + 64];
    orow[lane + 96] = acc3 * inv - REF[i*DIM + lane + 96];
}

extern "C" void kernel_launch(void* const* d_in, const int* in_sizes, int n_in,
                              void* d_out, int out_size) {
    const float* a = (const float*)d_in[0];
    const float* c = (const float*)d_in[1];
    const float *X, *REF;
    if (in_sizes[0] == NREF * DIM) { REF = a; X = c; }
    else                           { X = a;  REF = c; }
    float* out = (float*)d_out;

    int warps = B_*NPTS + NREF;
    aux_kernel<<<(warps*32 + 255) / 256, 256>>>(X, REF);

    dim3 cg(NPTS/64, NREF/64, B_);
    c_kernel<<<cg, 256>>>(X, REF);

    sinkhorn_cluster<<<2 * B_, 1024>>>();

    bary_kernel<<<dim3(NREF/8, B_), 256>>>(X, REF, out);
}